// round 6
// baseline (speedup 1.0000x reference)
#include <cuda_runtime.h>
#include <cuda_fp16.h>
#include <math.h>
#include <stdint.h>

#define CCH 512
#define HWT 4096
#define BATCH 2
#define NGROUPS 32
#define CPG 16

// ---------------- scratch (allocation-free) ----------------
__device__ __half  g_h[(size_t)BATCH * HWT * CCH];   // normalized, token-major
__device__ __half  g_q[(size_t)BATCH * HWT * CCH];
__device__ __half  g_k[(size_t)BATCH * HWT * CCH];
__device__ __half  g_v[(size_t)BATCH * CCH * HWT];   // channel-major
__device__ __half  g_o[(size_t)BATCH * HWT * CCH];   // attn out, token-major
__device__ __half  g_s[(size_t)BATCH * HWT * HWT];   // scores / probs
__device__ __half  g_w[4 * CCH * CCH];               // q_w, k_w, v_w, p_w fp16
__device__ float2  g_stats[BATCH * NGROUPS];

// ---------------- helpers ----------------
__device__ __forceinline__ uint32_t smem_u32(const void* p) {
    uint32_t a;
    asm("{ .reg .u64 t; cvta.to.shared.u64 t, %1; cvt.u32.u64 %0, t; }" : "=r"(a) : "l"(p));
    return a;
}
__device__ __forceinline__ void ldsm_x4(uint32_t& r0, uint32_t& r1, uint32_t& r2, uint32_t& r3,
                                        uint32_t addr) {
    asm volatile("ldmatrix.sync.aligned.m8n8.x4.shared.b16 {%0,%1,%2,%3}, [%4];"
                 : "=r"(r0), "=r"(r1), "=r"(r2), "=r"(r3) : "r"(addr));
}
__device__ __forceinline__ void mma_f16(float* c, const uint32_t* a, const uint32_t* b) {
    asm("mma.sync.aligned.m16n8k16.row.col.f32.f16.f16.f32 "
        "{%0,%1,%2,%3}, {%4,%5,%6,%7}, {%8,%9}, {%0,%1,%2,%3};"
        : "+f"(c[0]), "+f"(c[1]), "+f"(c[2]), "+f"(c[3])
        : "r"(a[0]), "r"(a[1]), "r"(a[2]), "r"(a[3]), "r"(b[0]), "r"(b[1]));
}

// ---------------- fp32 -> fp16 weight convert ----------------
__global__ void w2h_kernel(const float* __restrict__ s0, const float* __restrict__ s1,
                           const float* __restrict__ s2, const float* __restrict__ s3,
                           __half* __restrict__ dst) {
    const int i = blockIdx.x * blockDim.x + threadIdx.x;
    const int N = CCH * CCH;
    dst[i]         = __float2half_rn(s0[i]);
    dst[i + N]     = __float2half_rn(s1[i]);
    dst[i + 2 * N] = __float2half_rn(s2[i]);
    dst[i + 3 * N] = __float2half_rn(s3[i]);
}

// ---------------- GroupNorm stats ----------------
__global__ void gn_stats(const float* __restrict__ x, float2* __restrict__ st) {
    const int bg = blockIdx.x;
    const size_t base = (size_t)bg * CPG * HWT;
    const float4* xp = (const float4*)(x + base);
    const int N4 = CPG * HWT / 4;

    float s = 0.f, ss = 0.f;
    for (int i = threadIdx.x; i < N4; i += blockDim.x) {
        float4 v = xp[i];
        s  += v.x + v.y + v.z + v.w;
        ss += v.x * v.x + v.y * v.y + v.z * v.z + v.w * v.w;
    }
    __shared__ float rs[32], rss[32];
    #pragma unroll
    for (int o = 16; o > 0; o >>= 1) {
        s  += __shfl_xor_sync(~0u, s,  o);
        ss += __shfl_xor_sync(~0u, ss, o);
    }
    const int wid = threadIdx.x >> 5, lid = threadIdx.x & 31;
    if (lid == 0) { rs[wid] = s; rss[wid] = ss; }
    __syncthreads();
    if (threadIdx.x == 0) {
        const int nw = blockDim.x >> 5;
        float ts = 0.f, tss = 0.f;
        for (int i = 0; i < nw; i++) { ts += rs[i]; tss += rss[i]; }
        const float invN = 1.f / (float)(CPG * HWT);
        const float mean = ts * invN;
        const float var  = fmaxf(tss * invN - mean * mean, 0.f);
        st[bg] = make_float2(mean, rsqrtf(var + 1e-6f));
    }
}

// ---------------- GN apply + transpose -> token-major fp16 h ----------------
__global__ void gn_apply_t(const float* __restrict__ x,
                           const float* __restrict__ gw, const float* __restrict__ gb,
                           const float2* __restrict__ st, __half* __restrict__ ht) {
    __shared__ float tile[32][33];
    const int b = blockIdx.z;
    const int c0 = blockIdx.y * 32, t0 = blockIdx.x * 32;
    const float* xp = x + (size_t)b * CCH * HWT;
    __half* hp = ht + (size_t)b * HWT * CCH;

    #pragma unroll
    for (int j = threadIdx.y; j < 32; j += 8)
        tile[j][threadIdx.x] = xp[(size_t)(c0 + j) * HWT + t0 + threadIdx.x];
    __syncthreads();

    const int c = c0 + threadIdx.x;
    const float2 mv = st[b * NGROUPS + (c >> 4)];
    const float a  = mv.y * gw[c];
    const float bo = gb[c] - mv.x * a;
    #pragma unroll
    for (int j = threadIdx.y; j < 32; j += 8)
        hp[(size_t)(t0 + j) * CCH + c] = __float2half_rn(tile[threadIdx.x][j] * a + bo);
}

// ---------------- fp16 HMMA GEMM: CTA 128x256, warp 64x64, 3-stage cp.async ----------------
// out[m][n] = scale * sum_k A[m][k]*B[n][k] (+bias)(+res); A,B fp16 k-contiguous.
// BIAS: 0 none, 1 per-n, 2 per-m.  RES (float out only) adds res[m*ldo+n].
template<int BIAS, bool RES, typename OutT>
__global__ __launch_bounds__(256, 1)
void mma_gemm(const __half* __restrict__ A, const __half* __restrict__ B,
              const float* __restrict__ bias, const float* __restrict__ res,
              OutT* __restrict__ out,
              int lda, int ldb, int ldo, int K, float scale,
              size_t sA, size_t sB, size_t sO, size_t sR) {
    constexpr int STG_A = 16384;         // 128 rows x 128B (BK=64 fp16)
    constexpr int STG_B = 32768;         // 256 rows x 128B
    constexpr int NSTG = 3;
    extern __shared__ char smem[];       // [A0 A1 A2 | B0 B1 B2] = 144KB
    const uint32_t sb = smem_u32(smem);
    const uint32_t sbB = sb + NSTG * STG_A;

    const int bz = blockIdx.z;
    A += (size_t)bz * sA;
    B += (size_t)bz * sB;
    out += (size_t)bz * sO;
    if (RES) res += (size_t)bz * sR;

    const int m0 = blockIdx.y * 128;
    const int n0 = blockIdx.x * 256;
    const int tid = threadIdx.x;
    const int lane = tid & 31;
    const int wid = tid >> 5;
    const int wm = wid & 1;              // 2 x 64 rows
    const int wn = wid >> 1;             // 4 x 64 cols

    // ---- cp.async geometry: rows r0 + 32*it, 16B chunk cb ----
    const int r0 = tid >> 3;             // 0..31
    const int cb = tid & 7;
    const __half* gA = A + (size_t)(m0 + r0) * lda + cb * 8;
    const __half* gB = B + (size_t)(n0 + r0) * ldb + cb * 8;
    uint32_t soffA[4], soffB[8];
    #pragma unroll
    for (int it = 0; it < 4; it++) {
        const int row = r0 + 32 * it;
        soffA[it] = (uint32_t)row * 128u + (uint32_t)((cb ^ (row & 7)) << 4);
    }
    #pragma unroll
    for (int it = 0; it < 8; it++) {
        const int row = r0 + 32 * it;
        soffB[it] = (uint32_t)row * 128u + (uint32_t)((cb ^ (row & 7)) << 4);
    }

    // ---- ldmatrix geometry ----
    const int aRowB = wm * 64 + (lane & 15);           // + mi*16
    const int aCk = (lane >> 4) & 1;
    const int bRowB = wn * 64 + (lane & 7) + (((lane >> 4) & 1) << 3);  // + ni2*16
    const int bCk = (lane >> 3) & 1;
    const int xr = lane & 7;

    float acc[4][8][4];
    #pragma unroll
    for (int mi = 0; mi < 4; mi++)
        #pragma unroll
        for (int ni = 0; ni < 8; ni++)
            #pragma unroll
            for (int r = 0; r < 4; r++) acc[mi][ni][r] = 0.f;

    auto load_tile = [&](int i, int s) {
        const __half* ga = gA + (size_t)i * 64;
        const __half* gb_ = gB + (size_t)i * 64;
        const uint32_t sa = sb + s * STG_A;
        const uint32_t sbb = sbB + s * STG_B;
        #pragma unroll
        for (int it = 0; it < 4; it++)
            asm volatile("cp.async.cg.shared.global [%0], [%1], 16;"
                :: "r"(sa + soffA[it]), "l"(ga + (size_t)(32 * it) * lda) : "memory");
        #pragma unroll
        for (int it = 0; it < 8; it++)
            asm volatile("cp.async.cg.shared.global [%0], [%1], 16;"
                :: "r"(sbb + soffB[it]), "l"(gb_ + (size_t)(32 * it) * ldb) : "memory");
    };

    const int NT = K / 64;
    load_tile(0, 0);
    asm volatile("cp.async.commit_group;" ::: "memory");
    load_tile(1, 1);
    asm volatile("cp.async.commit_group;" ::: "memory");

    int stage = 0;
    for (int i = 0; i < NT; i++) {
        asm volatile("cp.async.wait_group %0;" :: "n"(1) : "memory");
        __syncthreads();
        if (i + 2 < NT) {
            int s2 = stage + 2; if (s2 >= NSTG) s2 -= NSTG;
            load_tile(i + 2, s2);
        }
        asm volatile("cp.async.commit_group;" ::: "memory");

        const uint32_t saS = sb + stage * STG_A;
        const uint32_t sbS = sbB + stage * STG_B;
        #pragma unroll
        for (int t = 0; t < 4; t++) {               // 4 k16 steps per BK=64
            uint32_t af[4][4], bf[8][2];
            #pragma unroll
            for (int mi = 0; mi < 4; mi++)
                ldsm_x4(af[mi][0], af[mi][1], af[mi][2], af[mi][3],
                        saS + (uint32_t)(aRowB + mi * 16) * 128u
                            + (uint32_t)(((2 * t + aCk) ^ xr) << 4));
            #pragma unroll
            for (int ni2 = 0; ni2 < 4; ni2++)
                ldsm_x4(bf[2 * ni2][0], bf[2 * ni2][1], bf[2 * ni2 + 1][0], bf[2 * ni2 + 1][1],
                        sbS + (uint32_t)(bRowB + ni2 * 16) * 128u
                            + (uint32_t)(((2 * t + bCk) ^ xr) << 4));
            #pragma unroll
            for (int mi = 0; mi < 4; mi++)
                #pragma unroll
                for (int ni = 0; ni < 8; ni++)
                    mma_f16(acc[mi][ni], af[mi], bf[ni]);
        }
        stage++; if (stage >= NSTG) stage -= NSTG;
    }

    // ---- epilogue ----
    #pragma unroll
    for (int mi = 0; mi < 4; mi++) {
        const int rbase = m0 + wm * 64 + mi * 16 + (lane >> 2);
        #pragma unroll
        for (int ni = 0; ni < 8; ni++) {
            const int cc = n0 + wn * 64 + ni * 8 + 2 * (lane & 3);
            #pragma unroll
            for (int hf = 0; hf < 2; hf++) {
                const int r = rbase + hf * 8;
                float vx = acc[mi][ni][hf * 2 + 0] * scale;
                float vy = acc[mi][ni][hf * 2 + 1] * scale;
                if (BIAS == 1) { vx += bias[cc]; vy += bias[cc + 1]; }
                else if (BIAS == 2) { const float bm = bias[r]; vx += bm; vy += bm; }
                if (sizeof(OutT) == 2) {
                    *(__half2*)((__half*)out + (size_t)r * ldo + cc) =
                        __floats2half2_rn(vx, vy);
                } else {
                    if (RES) {
                        float2 rr = *(const float2*)&res[(size_t)r * ldo + cc];
                        vx += rr.x; vy += rr.y;
                    }
                    float2 v; v.x = vx; v.y = vy;
                    *(float2*)((float*)out + (size_t)r * ldo + cc) = v;
                }
            }
        }
    }
}

// ---------------- fp16 row softmax (in place) ----------------
__global__ __launch_bounds__(256)
void softmax_kernel(__half* __restrict__ s) {
    const size_t row = blockIdx.x;
    __half2* p2 = (__half2*)(s + row * HWT);
    __shared__ float buf[HWT];
    __shared__ float red[32];
    float2* b2 = (float2*)buf;
    const int tid = threadIdx.x;
    const int wid = tid >> 5, lid = tid & 31;

    float mx = -1e30f;
    for (int i = tid; i < HWT / 2; i += 256) {
        float2 v = __half22float2(p2[i]);
        b2[i] = v;
        mx = fmaxf(mx, fmaxf(v.x, v.y));
    }
    #pragma unroll
    for (int o = 16; o > 0; o >>= 1) mx = fmaxf(mx, __shfl_xor_sync(~0u, mx, o));
    if (lid == 0) red[wid] = mx;
    __syncthreads();
    if (tid == 0) {
        float m2 = red[0];
        for (int i = 1; i < 8; i++) m2 = fmaxf(m2, red[i]);
        red[0] = m2;
    }
    __syncthreads();
    const float rowmax = red[0];
    __syncthreads();

    float sum = 0.f;
    for (int i = tid; i < HWT / 2; i += 256) {
        float2 v = b2[i];
        v.x = __expf(v.x - rowmax); v.y = __expf(v.y - rowmax);
        sum += v.x + v.y;
        b2[i] = v;
    }
    #pragma unroll
    for (int o = 16; o > 0; o >>= 1) sum += __shfl_xor_sync(~0u, sum, o);
    if (lid == 0) red[wid] = sum;
    __syncthreads();
    if (tid == 0) {
        float t = 0.f;
        for (int i = 0; i < 8; i++) t += red[i];
        red[0] = t;
    }
    __syncthreads();
    const float inv = 1.f / red[0];
    for (int i = tid; i < HWT / 2; i += 256) {
        float2 v = b2[i];
        p2[i] = __floats2half2_rn(v.x * inv, v.y * inv);
    }
}

// ---------------- launch ----------------
extern "C" void kernel_launch(void* const* d_in, const int* in_sizes, int n_in,
                              void* d_out, int out_size) {
    const float* x    = (const float*)d_in[0];
    const float* gn_w = (const float*)d_in[1];
    const float* gn_b = (const float*)d_in[2];
    const float* q_w  = (const float*)d_in[3];
    const float* q_b  = (const float*)d_in[4];
    const float* k_w  = (const float*)d_in[5];
    const float* k_b  = (const float*)d_in[6];
    const float* v_w  = (const float*)d_in[7];
    const float* v_b  = (const float*)d_in[8];
    const float* p_w  = (const float*)d_in[9];
    const float* p_b  = (const float*)d_in[10];
    float* out = (float*)d_out;

    __half *h, *q, *k, *v, *o, *s, *w;
    float2* st;
    cudaGetSymbolAddress((void**)&h, g_h);
    cudaGetSymbolAddress((void**)&q, g_q);
    cudaGetSymbolAddress((void**)&k, g_k);
    cudaGetSymbolAddress((void**)&v, g_v);
    cudaGetSymbolAddress((void**)&o, g_o);
    cudaGetSymbolAddress((void**)&s, g_s);
    cudaGetSymbolAddress((void**)&w, g_w);
    cudaGetSymbolAddress((void**)&st, g_stats);

    const int SMEM_T = 3 * (16384 + 32768);   // 147456
    cudaFuncSetAttribute(mma_gemm<0, false, __half>, cudaFuncAttributeMaxDynamicSharedMemorySize, SMEM_T);
    cudaFuncSetAttribute(mma_gemm<1, false, __half>, cudaFuncAttributeMaxDynamicSharedMemorySize, SMEM_T);
    cudaFuncSetAttribute(mma_gemm<2, false, __half>, cudaFuncAttributeMaxDynamicSharedMemorySize, SMEM_T);
    cudaFuncSetAttribute(mma_gemm<2, true, float>,   cudaFuncAttributeMaxDynamicSharedMemorySize, SMEM_T);

    const size_t TOK = (size_t)HWT * CCH;
    const size_t SS  = (size_t)HWT * HWT;
    const size_t CHW = (size_t)CCH * HWT;
    const int WN = CCH * CCH;
    const float att_scale = 0.04419417382415922f; // 1/sqrt(512)

    // 0. weights -> fp16
    w2h_kernel<<<WN / 256, 256>>>(q_w, k_w, v_w, p_w, w);
    __half* qw = w;
    __half* kw = w + WN;
    __half* vw = w + 2 * WN;
    __half* pw = w + 3 * WN;

    // 1. GroupNorm stats + apply/transpose -> h token-major fp16
    gn_stats<<<BATCH * NGROUPS, 512>>>(x, st);
    gn_apply_t<<<dim3(HWT / 32, CCH / 32, BATCH), dim3(32, 8)>>>(x, gn_w, gn_b, st, h);

    // 2. q, k token-major: M=HW, N=C, K=C
    dim3 gq(CCH / 256, HWT / 128, BATCH);
    mma_gemm<1, false, __half><<<gq, 256, SMEM_T>>>(h, qw, q_b, nullptr, q,
        CCH, CCH, CCH, CCH, 1.f, TOK, 0, TOK, 0);
    mma_gemm<1, false, __half><<<gq, 256, SMEM_T>>>(h, kw, k_b, nullptr, k,
        CCH, CCH, CCH, CCH, 1.f, TOK, 0, TOK, 0);

    // 3. v channel-major: M=C, N=HW, K=C  (A=v_w, B=h)
    dim3 gv(HWT / 256, CCH / 128, BATCH);
    mma_gemm<2, false, __half><<<gv, 256, SMEM_T>>>(vw, h, v_b, nullptr, v,
        CCH, CCH, HWT, CCH, 1.f, 0, TOK, TOK, 0);

    // 4. scores = scale * Q @ K^T : M=N=HW, K=C
    dim3 gs(HWT / 256, HWT / 128, BATCH);
    mma_gemm<0, false, __half><<<gs, 256, SMEM_T>>>(q, k, nullptr, nullptr, s,
        CCH, CCH, HWT, CCH, att_scale, TOK, TOK, SS, 0);

    // 5. softmax rows
    softmax_kernel<<<BATCH * HWT, 256>>>(s);

    // 6. o = attn @ V : M=HW, N=C, K=HW (B = v channel-major)
    dim3 ga(CCH / 256, HWT / 128, BATCH);
    mma_gemm<0, false, __half><<<ga, 256, SMEM_T>>>(s, v, nullptr, nullptr, o,
        HWT, HWT, CCH, HWT, 1.f, SS, TOK, TOK, 0);

    // 7. out = x + P @ o^T (channel-major): M=C, N=HW, K=C
    dim3 gp(HWT / 256, CCH / 128, BATCH);
    mma_gemm<2, true, float><<<gp, 256, SMEM_T>>>(pw, o, p_b, x, out,
        CCH, CCH, HWT, CCH, 1.f, 0, TOK, CHW, CHW);
}

// round 7
// speedup vs baseline: 1.1394x; 1.1394x over previous
#include <cuda_runtime.h>
#include <cuda_fp16.h>
#include <math.h>
#include <stdint.h>

#define CCH 512
#define HWT 4096
#define BATCH 2
#define NGROUPS 32
#define CPG 16

// ---------------- scratch (allocation-free) ----------------
__device__ __half  g_h[(size_t)BATCH * HWT * CCH];   // normalized, token-major
__device__ __half  g_q[(size_t)BATCH * HWT * CCH];
__device__ __half  g_k[(size_t)BATCH * HWT * CCH];
__device__ __half  g_v[(size_t)BATCH * CCH * HWT];   // channel-major
__device__ __half  g_o[(size_t)BATCH * HWT * CCH];   // attn out, token-major
__device__ __half  g_s[(size_t)BATCH * HWT * HWT];   // P = exp(logit)*2^-5, fp16
__device__ __half  g_w[4 * CCH * CCH];               // [q_w; k_w; v_w; p_w] fp16
__device__ float   g_bqkv[3 * CCH];                  // concat bias
__device__ float2  g_stats[BATCH * NGROUPS];

// ---------------- helpers ----------------
__device__ __forceinline__ uint32_t smem_u32(const void* p) {
    uint32_t a;
    asm("{ .reg .u64 t; cvta.to.shared.u64 t, %1; cvt.u32.u64 %0, t; }" : "=r"(a) : "l"(p));
    return a;
}
__device__ __forceinline__ void ldsm_x4(uint32_t& r0, uint32_t& r1, uint32_t& r2, uint32_t& r3,
                                        uint32_t addr) {
    asm volatile("ldmatrix.sync.aligned.m8n8.x4.shared.b16 {%0,%1,%2,%3}, [%4];"
                 : "=r"(r0), "=r"(r1), "=r"(r2), "=r"(r3) : "r"(addr));
}
__device__ __forceinline__ void mma_f16(float* c, const uint32_t* a, const uint32_t* b) {
    asm("mma.sync.aligned.m16n8k16.row.col.f32.f16.f16.f32 "
        "{%0,%1,%2,%3}, {%4,%5,%6,%7}, {%8,%9}, {%0,%1,%2,%3};"
        : "+f"(c[0]), "+f"(c[1]), "+f"(c[2]), "+f"(c[3])
        : "r"(a[0]), "r"(a[1]), "r"(a[2]), "r"(a[3]), "r"(b[0]), "r"(b[1]));
}

// ---------------- weight fp16 convert + bias concat ----------------
__global__ void w2h_kernel(const float* __restrict__ s0, const float* __restrict__ s1,
                           const float* __restrict__ s2, const float* __restrict__ s3,
                           __half* __restrict__ dst) {
    const int i = blockIdx.x * blockDim.x + threadIdx.x;
    const int N = CCH * CCH;
    dst[i]         = __float2half_rn(s0[i]);
    dst[i + N]     = __float2half_rn(s1[i]);
    dst[i + 2 * N] = __float2half_rn(s2[i]);
    dst[i + 3 * N] = __float2half_rn(s3[i]);
}
__global__ void bias_cat(const float* __restrict__ qb, const float* __restrict__ kb,
                         const float* __restrict__ vb, float* __restrict__ dst) {
    const int i = blockIdx.x * blockDim.x + threadIdx.x;
    const float* src = (i < CCH) ? qb : (i < 2 * CCH) ? kb : vb;
    dst[i] = src[i & (CCH - 1)];
}

// ---------------- GroupNorm stats ----------------
__global__ void gn_stats(const float* __restrict__ x, float2* __restrict__ st) {
    const int bg = blockIdx.x;
    const size_t base = (size_t)bg * CPG * HWT;
    const float4* xp = (const float4*)(x + base);
    const int N4 = CPG * HWT / 4;

    float s = 0.f, ss = 0.f;
    for (int i = threadIdx.x; i < N4; i += blockDim.x) {
        float4 v = xp[i];
        s  += v.x + v.y + v.z + v.w;
        ss += v.x * v.x + v.y * v.y + v.z * v.z + v.w * v.w;
    }
    __shared__ float rs[32], rss[32];
    #pragma unroll
    for (int o = 16; o > 0; o >>= 1) {
        s  += __shfl_xor_sync(~0u, s,  o);
        ss += __shfl_xor_sync(~0u, ss, o);
    }
    const int wid = threadIdx.x >> 5, lid = threadIdx.x & 31;
    if (lid == 0) { rs[wid] = s; rss[wid] = ss; }
    __syncthreads();
    if (threadIdx.x == 0) {
        const int nw = blockDim.x >> 5;
        float ts = 0.f, tss = 0.f;
        for (int i = 0; i < nw; i++) { ts += rs[i]; tss += rss[i]; }
        const float invN = 1.f / (float)(CPG * HWT);
        const float mean = ts * invN;
        const float var  = fmaxf(tss * invN - mean * mean, 0.f);
        st[bg] = make_float2(mean, rsqrtf(var + 1e-6f));
    }
}

// ---------------- GN apply + transpose -> token-major fp16 h ----------------
__global__ void gn_apply_t(const float* __restrict__ x,
                           const float* __restrict__ gw, const float* __restrict__ gb,
                           const float2* __restrict__ st, __half* __restrict__ ht) {
    __shared__ float tile[32][33];
    const int b = blockIdx.z;
    const int c0 = blockIdx.y * 32, t0 = blockIdx.x * 32;
    const float* xp = x + (size_t)b * CCH * HWT;
    __half* hp = ht + (size_t)b * HWT * CCH;

    #pragma unroll
    for (int j = threadIdx.y; j < 32; j += 8)
        tile[j][threadIdx.x] = xp[(size_t)(c0 + j) * HWT + t0 + threadIdx.x];
    __syncthreads();

    const int c = c0 + threadIdx.x;
    const float2 mv = st[b * NGROUPS + (c >> 4)];
    const float a  = mv.y * gw[c];
    const float bo = gb[c] - mv.x * a;
    #pragma unroll
    for (int j = threadIdx.y; j < 32; j += 8)
        hp[(size_t)(t0 + j) * CCH + c] = __float2half_rn(tile[threadIdx.x][j] * a + bo);
}

// ---------------- fp16 HMMA GEMM, CTA 128x128, 3-stage cp.async ----------------
// MODE 0: scores  -> out half = exp(acc*scale)*2^-5
// MODE 1: qkv     -> seg by n0: q/k token-major half (+bias), v transposed channel-major (+bias)
// MODE 2: attn@V  -> rowsum of A tiles, out half = acc / rowsum[m]
// MODE 3: proj    -> out float = acc + bias[m] + res[m][n]
template<int MODE>
__global__ __launch_bounds__(256, 2)
void mma_gemm(const __half* __restrict__ A, const __half* __restrict__ B,
              const float* __restrict__ bias, const float* __restrict__ res,
              void* __restrict__ outv, __half* __restrict__ outK, __half* __restrict__ outV,
              int lda, int ldb, int ldo, int K, float scale,
              size_t sA, size_t sB, size_t sO, size_t sR) {
    constexpr int STG = 16384;           // 128 rows x 128B (BK=64 fp16)
    constexpr int NSTG = 3;
    extern __shared__ char smem[];       // [A0 A1 A2 | B0 B1 B2 | rowsum]
    const uint32_t sb = smem_u32(smem);
    const uint32_t sbB = sb + NSTG * STG;
    float* rs_s = (float*)(smem + 2 * NSTG * STG);

    const int bz = blockIdx.z;
    A += (size_t)bz * sA;
    B += (size_t)bz * sB;
    if (MODE == 3) res += (size_t)bz * sR;
    if (MODE == 1) {
        outK += (size_t)bz * sO;
        outV += (size_t)bz * sO;
    }

    const int m0 = blockIdx.y * 128;
    const int n0 = blockIdx.x * 128;
    const int tid = threadIdx.x;
    const int lane = tid & 31;
    const int wid = tid >> 5;
    const int wm = wid & 1;              // 2 x 64 rows
    const int wn = wid >> 1;             // 4 x 32 cols

    // ---- cp.async geometry ----
    const int r0 = tid >> 3;             // 0..31
    const int cb = tid & 7;
    const __half* gA = A + (size_t)(m0 + r0) * lda + cb * 8;
    const __half* gB = B + (size_t)(n0 + r0) * ldb + cb * 8;
    uint32_t soff[4];
    #pragma unroll
    for (int it = 0; it < 4; it++) {
        const int row = r0 + 32 * it;
        soff[it] = (uint32_t)row * 128u + (uint32_t)((cb ^ (row & 7)) << 4);
    }

    // ---- ldmatrix geometry ----
    const int aRowB = wm * 64 + (lane & 15);
    const int aCk = (lane >> 4) & 1;
    const int bRowB = wn * 32 + (lane & 7) + (((lane >> 4) & 1) << 3);
    const int bCk = (lane >> 3) & 1;
    const int xr = lane & 7;

    // ---- rowsum geometry (MODE 2) ----
    const int srow = tid >> 1;           // 0..127
    const int shalf = tid & 1;
    uint32_t rsoff[4];
    if (MODE == 2) {
        #pragma unroll
        for (int c4 = 0; c4 < 4; c4++) {
            const int ch = shalf * 4 + c4;
            rsoff[c4] = (uint32_t)srow * 128u + (uint32_t)((ch ^ (srow & 7)) << 4);
        }
    }
    float rsum = 0.f;

    float acc[4][4][4];
    #pragma unroll
    for (int mi = 0; mi < 4; mi++)
        #pragma unroll
        for (int ni = 0; ni < 4; ni++)
            #pragma unroll
            for (int r = 0; r < 4; r++) acc[mi][ni][r] = 0.f;

    auto load_tile = [&](int i, int s) {
        const __half* ga = gA + (size_t)i * 64;
        const __half* gb_ = gB + (size_t)i * 64;
        const uint32_t sa = sb + s * STG;
        const uint32_t sbb = sbB + s * STG;
        #pragma unroll
        for (int it = 0; it < 4; it++)
            asm volatile("cp.async.cg.shared.global [%0], [%1], 16;"
                :: "r"(sa + soff[it]), "l"(ga + (size_t)(32 * it) * lda) : "memory");
        #pragma unroll
        for (int it = 0; it < 4; it++)
            asm volatile("cp.async.cg.shared.global [%0], [%1], 16;"
                :: "r"(sbb + soff[it]), "l"(gb_ + (size_t)(32 * it) * ldb) : "memory");
    };

    const int NT = K / 64;
    load_tile(0, 0);
    asm volatile("cp.async.commit_group;" ::: "memory");
    load_tile(1, 1);
    asm volatile("cp.async.commit_group;" ::: "memory");

    int stage = 0;
    for (int i = 0; i < NT; i++) {
        asm volatile("cp.async.wait_group %0;" :: "n"(1) : "memory");
        __syncthreads();
        if (i + 2 < NT) {
            int s2 = stage + 2; if (s2 >= NSTG) s2 -= NSTG;
            load_tile(i + 2, s2);
        }
        asm volatile("cp.async.commit_group;" ::: "memory");

        if (MODE == 2) {
            // accumulate row sums of this A tile (P values)
            const char* base = smem + stage * STG;
            #pragma unroll
            for (int c4 = 0; c4 < 4; c4++) {
                uint4 d = *(const uint4*)(base + rsoff[c4]);
                float2 f0 = __half22float2(*(__half2*)&d.x);
                float2 f1 = __half22float2(*(__half2*)&d.y);
                float2 f2 = __half22float2(*(__half2*)&d.z);
                float2 f3 = __half22float2(*(__half2*)&d.w);
                rsum += (f0.x + f0.y) + (f1.x + f1.y) + (f2.x + f2.y) + (f3.x + f3.y);
            }
        }

        const uint32_t saS = sb + stage * STG;
        const uint32_t sbS = sbB + stage * STG;
        #pragma unroll
        for (int t = 0; t < 4; t++) {
            uint32_t af[4][4], bf[4][2];
            #pragma unroll
            for (int mi = 0; mi < 4; mi++)
                ldsm_x4(af[mi][0], af[mi][1], af[mi][2], af[mi][3],
                        saS + (uint32_t)(aRowB + mi * 16) * 128u
                            + (uint32_t)(((2 * t + aCk) ^ xr) << 4));
            #pragma unroll
            for (int ni2 = 0; ni2 < 2; ni2++)
                ldsm_x4(bf[2 * ni2][0], bf[2 * ni2][1], bf[2 * ni2 + 1][0], bf[2 * ni2 + 1][1],
                        sbS + (uint32_t)(bRowB + ni2 * 16) * 128u
                            + (uint32_t)(((2 * t + bCk) ^ xr) << 4));
            #pragma unroll
            for (int mi = 0; mi < 4; mi++)
                #pragma unroll
                for (int ni = 0; ni < 4; ni++)
                    mma_f16(acc[mi][ni], af[mi], bf[ni]);
        }
        stage++; if (stage >= NSTG) stage -= NSTG;
    }

    if (MODE == 2) {
        rsum += __shfl_xor_sync(~0u, rsum, 1);
        rs_s[srow] = rsum;               // both halves write same value
        __syncthreads();
    }

    // ---- epilogue ----
    #pragma unroll
    for (int mi = 0; mi < 4; mi++) {
        const int rl0 = wm * 64 + mi * 16 + (lane >> 2);   // local row
        #pragma unroll
        for (int ni = 0; ni < 4; ni++) {
            const int ccg = n0 + wn * 32 + ni * 8 + 2 * (lane & 3);
            #pragma unroll
            for (int hf = 0; hf < 2; hf++) {
                const int rl = rl0 + hf * 8;
                const int r = m0 + rl;
                float vx = acc[mi][ni][hf * 2 + 0];
                float vy = acc[mi][ni][hf * 2 + 1];
                if (MODE == 0) {
                    vx = __expf(vx * scale) * 0.03125f;
                    vy = __expf(vy * scale) * 0.03125f;
                    __half* o = (__half*)outv + (size_t)bz * sO;
                    *(__half2*)(o + (size_t)r * ldo + ccg) = __floats2half2_rn(vx, vy);
                } else if (MODE == 1) {
                    vx += bias[ccg]; vy += bias[ccg + 1];
                    const int seg = n0 >> 9;
                    const int nc = ccg & (CCH - 1);
                    if (seg < 2) {
                        __half* o = (seg == 0) ? (__half*)outv + (size_t)bz * sO : outK;
                        *(__half2*)(o + (size_t)r * CCH + nc) = __floats2half2_rn(vx, vy);
                    } else {
                        outV[(size_t)nc * HWT + r]       = __float2half_rn(vx);
                        outV[(size_t)(nc + 1) * HWT + r] = __float2half_rn(vy);
                    }
                } else if (MODE == 2) {
                    const float inv = 1.f / rs_s[rl];
                    __half* o = (__half*)outv + (size_t)bz * sO;
                    *(__half2*)(o + (size_t)r * ldo + ccg) =
                        __floats2half2_rn(vx * inv, vy * inv);
                } else {
                    const float bm = bias[r];
                    float2 rr = *(const float2*)&res[(size_t)r * ldo + ccg];
                    float* o = (float*)outv + (size_t)bz * sO;
                    float2 v; v.x = vx + bm + rr.x; v.y = vy + bm + rr.y;
                    *(float2*)(o + (size_t)r * ldo + ccg) = v;
                }
            }
        }
    }
}

// ---------------- launch ----------------
extern "C" void kernel_launch(void* const* d_in, const int* in_sizes, int n_in,
                              void* d_out, int out_size) {
    const float* x    = (const float*)d_in[0];
    const float* gn_w = (const float*)d_in[1];
    const float* gn_b = (const float*)d_in[2];
    const float* q_w  = (const float*)d_in[3];
    const float* q_b  = (const float*)d_in[4];
    const float* k_w  = (const float*)d_in[5];
    const float* k_b  = (const float*)d_in[6];
    const float* v_w  = (const float*)d_in[7];
    const float* v_b  = (const float*)d_in[8];
    const float* p_w  = (const float*)d_in[9];
    const float* p_b  = (const float*)d_in[10];
    float* out = (float*)d_out;

    __half *h, *q, *k, *v, *o, *s, *w;
    float *bq;
    float2* st;
    cudaGetSymbolAddress((void**)&h, g_h);
    cudaGetSymbolAddress((void**)&q, g_q);
    cudaGetSymbolAddress((void**)&k, g_k);
    cudaGetSymbolAddress((void**)&v, g_v);
    cudaGetSymbolAddress((void**)&o, g_o);
    cudaGetSymbolAddress((void**)&s, g_s);
    cudaGetSymbolAddress((void**)&w, g_w);
    cudaGetSymbolAddress((void**)&bq, g_bqkv);
    cudaGetSymbolAddress((void**)&st, g_stats);

    const int SMEM_T = 3 * 2 * 16384 + 512;   // 98816
    cudaFuncSetAttribute(mma_gemm<0>, cudaFuncAttributeMaxDynamicSharedMemorySize, SMEM_T);
    cudaFuncSetAttribute(mma_gemm<1>, cudaFuncAttributeMaxDynamicSharedMemorySize, SMEM_T);
    cudaFuncSetAttribute(mma_gemm<2>, cudaFuncAttributeMaxDynamicSharedMemorySize, SMEM_T);
    cudaFuncSetAttribute(mma_gemm<3>, cudaFuncAttributeMaxDynamicSharedMemorySize, SMEM_T);

    const size_t TOK = (size_t)HWT * CCH;
    const size_t SS  = (size_t)HWT * HWT;
    const size_t CHW = (size_t)CCH * HWT;
    const int WN = CCH * CCH;
    const float att_scale = 0.04419417382415922f; // 1/sqrt(512)

    // 0. weights -> fp16 (concat [q;k;v;p]), bias concat
    w2h_kernel<<<WN / 256, 256>>>(q_w, k_w, v_w, p_w, w);
    bias_cat<<<3 * CCH / 256, 256>>>(q_b, k_b, v_b, bq);
    __half* pw = w + 3 * WN;

    // 1. GroupNorm stats + apply/transpose -> h token-major fp16
    gn_stats<<<BATCH * NGROUPS, 512>>>(x, st);
    gn_apply_t<<<dim3(HWT / 32, CCH / 32, BATCH), dim3(32, 8)>>>(x, gn_w, gn_b, st, h);

    // 2. fused qkv: M=HW, N=1536, K=512; v written channel-major transposed
    dim3 gq(3 * CCH / 128, HWT / 128, BATCH);
    mma_gemm<1><<<gq, 256, SMEM_T>>>(h, w, bq, nullptr, q, k, v,
        CCH, CCH, CCH, CCH, 1.f, TOK, 0, TOK, 0);

    // 3. P = exp(scale * Q@K^T)*2^-5 : M=N=HW, K=C
    dim3 gs(HWT / 128, HWT / 128, BATCH);
    mma_gemm<0><<<gs, 256, SMEM_T>>>(q, k, nullptr, nullptr, s, nullptr, nullptr,
        CCH, CCH, HWT, CCH, att_scale, TOK, TOK, SS, 0);

    // 4. o = (P@V) / rowsum(P) : M=HW, N=C, K=HW
    dim3 ga(CCH / 128, HWT / 128, BATCH);
    mma_gemm<2><<<ga, 256, SMEM_T>>>(s, v, nullptr, nullptr, o, nullptr, nullptr,
        HWT, HWT, CCH, HWT, 1.f, SS, TOK, TOK, 0);

    // 5. out = x + P_w @ o^T (channel-major): M=C, N=HW, K=C
    dim3 gp(HWT / 128, CCH / 128, BATCH);
    mma_gemm<3><<<gp, 256, SMEM_T>>>(pw, o, p_b, x, out, nullptr, nullptr,
        CCH, CCH, HWT, CCH, 1.f, 0, TOK, CHW, CHW);
}

// round 8
// speedup vs baseline: 1.1396x; 1.0001x over previous
#include <cuda_runtime.h>
#include <cuda_fp16.h>
#include <math.h>
#include <stdint.h>

#define CCH 512
#define HWT 4096
#define BATCH 2
#define NGROUPS 32
#define CPG 16

// ---------------- scratch (allocation-free) ----------------
__device__ __half  g_h[(size_t)BATCH * HWT * CCH];   // normalized, token-major
__device__ __half  g_q[(size_t)BATCH * HWT * CCH];
__device__ __half  g_k[(size_t)BATCH * HWT * CCH];
__device__ __half  g_v[(size_t)BATCH * CCH * HWT];   // channel-major
__device__ __half  g_o[(size_t)BATCH * HWT * CCH];   // attn out, token-major
__device__ __half  g_s[(size_t)BATCH * HWT * HWT];   // P = exp(logit)*2^-5, fp16
__device__ __half  g_w[4 * CCH * CCH];               // [q_w; k_w; v_w; p_w] fp16
__device__ float   g_bqkv[3 * CCH];                  // concat bias
__device__ float2  g_part[BATCH * NGROUPS * 4];      // partial {sum, sumsq}

// ---------------- helpers ----------------
__device__ __forceinline__ uint32_t smem_u32(const void* p) {
    uint32_t a;
    asm("{ .reg .u64 t; cvta.to.shared.u64 t, %1; cvt.u32.u64 %0, t; }" : "=r"(a) : "l"(p));
    return a;
}
__device__ __forceinline__ void ldsm_x4(uint32_t& r0, uint32_t& r1, uint32_t& r2, uint32_t& r3,
                                        uint32_t addr) {
    asm volatile("ldmatrix.sync.aligned.m8n8.x4.shared.b16 {%0,%1,%2,%3}, [%4];"
                 : "=r"(r0), "=r"(r1), "=r"(r2), "=r"(r3) : "r"(addr));
}
__device__ __forceinline__ void mma_f16(float* c, const uint32_t* a, const uint32_t* b) {
    asm("mma.sync.aligned.m16n8k16.row.col.f32.f16.f16.f32 "
        "{%0,%1,%2,%3}, {%4,%5,%6,%7}, {%8,%9}, {%0,%1,%2,%3};"
        : "+f"(c[0]), "+f"(c[1]), "+f"(c[2]), "+f"(c[3])
        : "r"(a[0]), "r"(a[1]), "r"(a[2]), "r"(a[3]), "r"(b[0]), "r"(b[1]));
}

// ---------------- weight fp16 convert + bias concat ----------------
__global__ void w2h_kernel(const float* __restrict__ s0, const float* __restrict__ s1,
                           const float* __restrict__ s2, const float* __restrict__ s3,
                           __half* __restrict__ dst) {
    const int i = blockIdx.x * blockDim.x + threadIdx.x;
    const int N = CCH * CCH;
    dst[i]         = __float2half_rn(s0[i]);
    dst[i + N]     = __float2half_rn(s1[i]);
    dst[i + 2 * N] = __float2half_rn(s2[i]);
    dst[i + 3 * N] = __float2half_rn(s3[i]);
}
__global__ void bias_cat(const float* __restrict__ qb, const float* __restrict__ kb,
                         const float* __restrict__ vb, float* __restrict__ dst) {
    const int i = blockIdx.x * blockDim.x + threadIdx.x;
    const float* src = (i < CCH) ? qb : (i < 2 * CCH) ? kb : vb;
    dst[i] = src[i & (CCH - 1)];
}

// ---------------- GroupNorm partial sums (256 CTAs) ----------------
__global__ __launch_bounds__(256)
void gn_part(const float* __restrict__ x, float2* __restrict__ part) {
    const int pb = blockIdx.x;            // 0..255
    const int bg = pb >> 2, qt = pb & 3;
    const float4* xp = (const float4*)(x + (size_t)bg * CPG * HWT) + qt * (CPG * HWT / 16);
    const int N4 = CPG * HWT / 16;        // 4096 float4

    float s = 0.f, ss = 0.f;
    for (int i = threadIdx.x; i < N4; i += 256) {
        float4 v = xp[i];
        s  += v.x + v.y + v.z + v.w;
        ss += v.x * v.x + v.y * v.y + v.z * v.z + v.w * v.w;
    }
    __shared__ float rs[8], rss[8];
    #pragma unroll
    for (int o = 16; o > 0; o >>= 1) {
        s  += __shfl_xor_sync(~0u, s,  o);
        ss += __shfl_xor_sync(~0u, ss, o);
    }
    const int wid = threadIdx.x >> 5, lid = threadIdx.x & 31;
    if (lid == 0) { rs[wid] = s; rss[wid] = ss; }
    __syncthreads();
    if (threadIdx.x == 0) {
        float ts = 0.f, tss = 0.f;
        #pragma unroll
        for (int i = 0; i < 8; i++) { ts += rs[i]; tss += rss[i]; }
        part[pb] = make_float2(ts, tss);
    }
}

// ---------------- GN apply + transpose -> token-major fp16 h ----------------
// 64c x 64t tiles, stats finalized in-block from partials
__global__ __launch_bounds__(256)
void gn_apply_t(const float* __restrict__ x,
                const float* __restrict__ gw, const float* __restrict__ gb,
                const float2* __restrict__ part, __half* __restrict__ ht) {
    __shared__ float tile[64][65];
    __shared__ float2 stg[4];             // {mean, inv} per 16-ch group
    __shared__ float gwS[64], gbS[64];
    const int b = blockIdx.z;
    const int c0 = blockIdx.y * 64, t0 = blockIdx.x * 64;
    const float* xp = x + (size_t)b * CCH * HWT;
    __half* hp = ht + (size_t)b * HWT * CCH;
    const int tid = threadIdx.x;

    if (tid < 4) {
        const int g = b * NGROUPS + (c0 >> 4) + tid;
        float s = 0.f, ss = 0.f;
        #pragma unroll
        for (int q = 0; q < 4; q++) {
            float2 p = part[g * 4 + q];
            s += p.x; ss += p.y;
        }
        const float invN = 1.f / (float)(CPG * HWT);
        const float mean = s * invN;
        const float var  = fmaxf(ss * invN - mean * mean, 0.f);
        stg[tid] = make_float2(mean, rsqrtf(var + 1e-6f));
    }
    if (tid < 64) { gwS[tid] = gw[c0 + tid]; gbS[tid] = gb[c0 + tid]; }

    // load 64 rows x 16 float4
    const int r = tid >> 2, q = tid & 3;
    const float4* xr = (const float4*)(xp + (size_t)(c0 + r) * HWT) + (t0 >> 2);
    #pragma unroll
    for (int i = 0; i < 4; i++) {
        float4 v = xr[q * 4 + i];
        tile[r][q * 16 + i * 4 + 0] = v.x;
        tile[r][q * 16 + i * 4 + 1] = v.y;
        tile[r][q * 16 + i * 4 + 2] = v.z;
        tile[r][q * 16 + i * 4 + 3] = v.w;
    }
    __syncthreads();

    // write transposed: 64 t-rows x 32 half2
    #pragma unroll
    for (int p = 0; p < 4; p++) {
        const int tr = p * 16 + (tid >> 4);
        __half2* hrow = (__half2*)(hp + (size_t)(t0 + tr) * CCH + c0);
        #pragma unroll
        for (int qq = 0; qq < 2; qq++) {
            const int c2 = (tid & 15) + 16 * qq;       // half2 index, c = 2*c2
            const int cl0 = 2 * c2, cl1 = 2 * c2 + 1;
            const float2 mv0 = stg[cl0 >> 4];
            const float2 mv1 = stg[cl1 >> 4];
            const float a0 = mv0.y * gwS[cl0], b0 = gbS[cl0] - mv0.x * a0;
            const float a1 = mv1.y * gwS[cl1], b1 = gbS[cl1] - mv1.x * a1;
            hrow[c2] = __floats2half2_rn(tile[cl0][tr] * a0 + b0,
                                         tile[cl1][tr] * a1 + b1);
        }
    }
}

// ---------------- fp16 HMMA GEMM, CTA 128x128, 3-stage cp.async ----------------
// MODE 0: scores  -> out half = exp(acc*scale)*2^-5
// MODE 1: qkv     -> seg by n0: q/k token-major (+bias); v seg staged via smem,
//                    written transposed channel-major coalesced (+bias)
// MODE 2: attn@V  -> rowsum of A tiles, out half = acc / rowsum[m]
// MODE 3: proj    -> out float = acc + bias[m] + res[m][n]
template<int MODE>
__global__ __launch_bounds__(256, 2)
void mma_gemm(const __half* __restrict__ A, const __half* __restrict__ B,
              const float* __restrict__ bias, const float* __restrict__ res,
              void* __restrict__ outv, __half* __restrict__ outK, __half* __restrict__ outV,
              int lda, int ldb, int ldo, int K, float scale,
              size_t sA, size_t sB, size_t sO, size_t sR) {
    constexpr int STG = 16384;           // 128 rows x 128B (BK=64 fp16)
    constexpr int NSTG = 3;
    extern __shared__ char smem[];       // [A0 A1 A2 | B0 B1 B2 | rowsum]
    const uint32_t sb = smem_u32(smem);
    const uint32_t sbB = sb + NSTG * STG;
    float* rs_s = (float*)(smem + 2 * NSTG * STG);

    const int bz = blockIdx.z;
    A += (size_t)bz * sA;
    B += (size_t)bz * sB;
    if (MODE == 3) res += (size_t)bz * sR;
    if (MODE == 1) {
        outK += (size_t)bz * sO;
        outV += (size_t)bz * sO;
    }

    const int m0 = blockIdx.y * 128;
    const int n0 = blockIdx.x * 128;
    const int tid = threadIdx.x;
    const int lane = tid & 31;
    const int wid = tid >> 5;
    const int wm = wid & 1;              // 2 x 64 rows
    const int wn = wid >> 1;             // 4 x 32 cols

    // ---- cp.async geometry ----
    const int r0 = tid >> 3;             // 0..31
    const int cb = tid & 7;
    const __half* gA = A + (size_t)(m0 + r0) * lda + cb * 8;
    const __half* gB = B + (size_t)(n0 + r0) * ldb + cb * 8;
    uint32_t soff[4];
    #pragma unroll
    for (int it = 0; it < 4; it++) {
        const int row = r0 + 32 * it;
        soff[it] = (uint32_t)row * 128u + (uint32_t)((cb ^ (row & 7)) << 4);
    }

    // ---- ldmatrix geometry ----
    const int aRowB = wm * 64 + (lane & 15);
    const int aCk = (lane >> 4) & 1;
    const int bRowB = wn * 32 + (lane & 7) + (((lane >> 4) & 1) << 3);
    const int bCk = (lane >> 3) & 1;
    const int xr = lane & 7;

    // ---- rowsum geometry (MODE 2) ----
    const int srow = tid >> 1;
    const int shalf = tid & 1;
    uint32_t rsoff[4];
    if (MODE == 2) {
        #pragma unroll
        for (int c4 = 0; c4 < 4; c4++) {
            const int ch = shalf * 4 + c4;
            rsoff[c4] = (uint32_t)srow * 128u + (uint32_t)((ch ^ (srow & 7)) << 4);
        }
    }
    float rsum = 0.f;

    float acc[4][4][4];
    #pragma unroll
    for (int mi = 0; mi < 4; mi++)
        #pragma unroll
        for (int ni = 0; ni < 4; ni++)
            #pragma unroll
            for (int r = 0; r < 4; r++) acc[mi][ni][r] = 0.f;

    auto load_tile = [&](int i, int s) {
        const __half* ga = gA + (size_t)i * 64;
        const __half* gb_ = gB + (size_t)i * 64;
        const uint32_t sa = sb + s * STG;
        const uint32_t sbb = sbB + s * STG;
        #pragma unroll
        for (int it = 0; it < 4; it++)
            asm volatile("cp.async.cg.shared.global [%0], [%1], 16;"
                :: "r"(sa + soff[it]), "l"(ga + (size_t)(32 * it) * lda) : "memory");
        #pragma unroll
        for (int it = 0; it < 4; it++)
            asm volatile("cp.async.cg.shared.global [%0], [%1], 16;"
                :: "r"(sbb + soff[it]), "l"(gb_ + (size_t)(32 * it) * ldb) : "memory");
    };

    const int NT = K / 64;
    load_tile(0, 0);
    asm volatile("cp.async.commit_group;" ::: "memory");
    load_tile(1, 1);
    asm volatile("cp.async.commit_group;" ::: "memory");

    int stage = 0;
    for (int i = 0; i < NT; i++) {
        asm volatile("cp.async.wait_group %0;" :: "n"(1) : "memory");
        __syncthreads();
        if (i + 2 < NT) {
            int s2 = stage + 2; if (s2 >= NSTG) s2 -= NSTG;
            load_tile(i + 2, s2);
        }
        asm volatile("cp.async.commit_group;" ::: "memory");

        if (MODE == 2) {
            const char* base = smem + stage * STG;
            #pragma unroll
            for (int c4 = 0; c4 < 4; c4++) {
                uint4 d = *(const uint4*)(base + rsoff[c4]);
                float2 f0 = __half22float2(*(__half2*)&d.x);
                float2 f1 = __half22float2(*(__half2*)&d.y);
                float2 f2 = __half22float2(*(__half2*)&d.z);
                float2 f3 = __half22float2(*(__half2*)&d.w);
                rsum += (f0.x + f0.y) + (f1.x + f1.y) + (f2.x + f2.y) + (f3.x + f3.y);
            }
        }

        const uint32_t saS = sb + stage * STG;
        const uint32_t sbS = sbB + stage * STG;
        #pragma unroll
        for (int t = 0; t < 4; t++) {
            uint32_t af[4][4], bf[4][2];
            #pragma unroll
            for (int mi = 0; mi < 4; mi++)
                ldsm_x4(af[mi][0], af[mi][1], af[mi][2], af[mi][3],
                        saS + (uint32_t)(aRowB + mi * 16) * 128u
                            + (uint32_t)(((2 * t + aCk) ^ xr) << 4));
            #pragma unroll
            for (int ni2 = 0; ni2 < 2; ni2++)
                ldsm_x4(bf[2 * ni2][0], bf[2 * ni2][1], bf[2 * ni2 + 1][0], bf[2 * ni2 + 1][1],
                        sbS + (uint32_t)(bRowB + ni2 * 16) * 128u
                            + (uint32_t)(((2 * t + bCk) ^ xr) << 4));
            #pragma unroll
            for (int mi = 0; mi < 4; mi++)
                #pragma unroll
                for (int ni = 0; ni < 4; ni++)
                    mma_f16(acc[mi][ni], af[mi], bf[ni]);
        }
        stage++; if (stage >= NSTG) stage -= NSTG;
    }

    if (MODE == 2) {
        rsum += __shfl_xor_sync(~0u, rsum, 1);
        rs_s[srow] = rsum;
        __syncthreads();
    }

    // ---- MODE 1, v segment: smem-staged transpose for coalesced stores ----
    if (MODE == 1 && (n0 >> 9) == 2) {
        asm volatile("cp.async.wait_group 0;" ::: "memory");
        __syncthreads();
        __half* st = (__half*)smem;
        constexpr int SSTR = 136;        // half stride, padded
        #pragma unroll
        for (int mi = 0; mi < 4; mi++) {
            const int rl0 = wm * 64 + mi * 16 + (lane >> 2);
            #pragma unroll
            for (int ni = 0; ni < 4; ni++) {
                const int ccl = wn * 32 + ni * 8 + 2 * (lane & 3);   // local col
                const int ccg = n0 + ccl;
                #pragma unroll
                for (int hf = 0; hf < 2; hf++) {
                    const int rl = rl0 + hf * 8;
                    st[ccl * SSTR + rl]       = __float2half_rn(acc[mi][ni][hf * 2 + 0] + bias[ccg]);
                    st[(ccl + 1) * SSTR + rl] = __float2half_rn(acc[mi][ni][hf * 2 + 1] + bias[ccg + 1]);
                }
            }
        }
        __syncthreads();
        const int nc0 = n0 - 1024;       // channel base within 512
        #pragma unroll
        for (int p = 0; p < 8; p++) {
            const int cl = p * 16 + (tid >> 4);
            __half2* orow = (__half2*)(outV + (size_t)(nc0 + cl) * HWT + m0);
            #pragma unroll
            for (int q = 0; q < 4; q++) {
                const int t2 = (tid & 15) + 16 * q;
                orow[t2] = *(__half2*)&st[cl * SSTR + 2 * t2];
            }
        }
        return;
    }

    // ---- epilogue (other modes / segments) ----
    #pragma unroll
    for (int mi = 0; mi < 4; mi++) {
        const int rl0 = wm * 64 + mi * 16 + (lane >> 2);
        #pragma unroll
        for (int ni = 0; ni < 4; ni++) {
            const int ccg = n0 + wn * 32 + ni * 8 + 2 * (lane & 3);
            #pragma unroll
            for (int hf = 0; hf < 2; hf++) {
                const int rl = rl0 + hf * 8;
                const int r = m0 + rl;
                float vx = acc[mi][ni][hf * 2 + 0];
                float vy = acc[mi][ni][hf * 2 + 1];
                if (MODE == 0) {
                    vx = __expf(vx * scale) * 0.03125f;
                    vy = __expf(vy * scale) * 0.03125f;
                    __half* o = (__half*)outv + (size_t)bz * sO;
                    *(__half2*)(o + (size_t)r * ldo + ccg) = __floats2half2_rn(vx, vy);
                } else if (MODE == 1) {
                    vx += bias[ccg]; vy += bias[ccg + 1];
                    const int nc = ccg & (CCH - 1);
                    __half* o = ((n0 >> 9) == 0) ? (__half*)outv + (size_t)bz * sO : outK;
                    *(__half2*)(o + (size_t)r * CCH + nc) = __floats2half2_rn(vx, vy);
                } else if (MODE == 2) {
                    const float inv = 1.f / rs_s[rl];
                    __half* o = (__half*)outv + (size_t)bz * sO;
                    *(__half2*)(o + (size_t)r * ldo + ccg) =
                        __floats2half2_rn(vx * inv, vy * inv);
                } else {
                    const float bm = bias[r];
                    float2 rr = *(const float2*)&res[(size_t)r * ldo + ccg];
                    float* o = (float*)outv + (size_t)bz * sO;
                    float2 v; v.x = vx + bm + rr.x; v.y = vy + bm + rr.y;
                    *(float2*)(o + (size_t)r * ldo + ccg) = v;
                }
            }
        }
    }
}

// ---------------- launch ----------------
extern "C" void kernel_launch(void* const* d_in, const int* in_sizes, int n_in,
                              void* d_out, int out_size) {
    const float* x    = (const float*)d_in[0];
    const float* gn_w = (const float*)d_in[1];
    const float* gn_b = (const float*)d_in[2];
    const float* q_w  = (const float*)d_in[3];
    const float* q_b  = (const float*)d_in[4];
    const float* k_w  = (const float*)d_in[5];
    const float* k_b  = (const float*)d_in[6];
    const float* v_w  = (const float*)d_in[7];
    const float* v_b  = (const float*)d_in[8];
    const float* p_w  = (const float*)d_in[9];
    const float* p_b  = (const float*)d_in[10];
    float* out = (float*)d_out;

    __half *h, *q, *k, *v, *o, *s, *w;
    float *bq;
    float2* part;
    cudaGetSymbolAddress((void**)&h, g_h);
    cudaGetSymbolAddress((void**)&q, g_q);
    cudaGetSymbolAddress((void**)&k, g_k);
    cudaGetSymbolAddress((void**)&v, g_v);
    cudaGetSymbolAddress((void**)&o, g_o);
    cudaGetSymbolAddress((void**)&s, g_s);
    cudaGetSymbolAddress((void**)&w, g_w);
    cudaGetSymbolAddress((void**)&bq, g_bqkv);
    cudaGetSymbolAddress((void**)&part, g_part);

    const int SMEM_T = 3 * 2 * 16384 + 512;   // 98816
    cudaFuncSetAttribute(mma_gemm<0>, cudaFuncAttributeMaxDynamicSharedMemorySize, SMEM_T);
    cudaFuncSetAttribute(mma_gemm<1>, cudaFuncAttributeMaxDynamicSharedMemorySize, SMEM_T);
    cudaFuncSetAttribute(mma_gemm<2>, cudaFuncAttributeMaxDynamicSharedMemorySize, SMEM_T);
    cudaFuncSetAttribute(mma_gemm<3>, cudaFuncAttributeMaxDynamicSharedMemorySize, SMEM_T);

    const size_t TOK = (size_t)HWT * CCH;
    const size_t SS  = (size_t)HWT * HWT;
    const size_t CHW = (size_t)CCH * HWT;
    const int WN = CCH * CCH;
    const float att_scale = 0.04419417382415922f; // 1/sqrt(512)

    // 0. weights -> fp16 (concat [q;k;v;p]), bias concat
    w2h_kernel<<<WN / 256, 256>>>(q_w, k_w, v_w, p_w, w);
    bias_cat<<<3 * CCH / 256, 256>>>(q_b, k_b, v_b, bq);
    __half* pw = w + 3 * WN;

    // 1. GroupNorm partials + apply/transpose -> h token-major fp16
    gn_part<<<BATCH * NGROUPS * 4, 256>>>(x, part);
    gn_apply_t<<<dim3(HWT / 64, CCH / 64, BATCH), 256>>>(x, gn_w, gn_b, part, h);

    // 2. fused qkv: M=HW, N=1536, K=512; v written channel-major transposed
    dim3 gq(3 * CCH / 128, HWT / 128, BATCH);
    mma_gemm<1><<<gq, 256, SMEM_T>>>(h, w, bq, nullptr, q, k, v,
        CCH, CCH, CCH, CCH, 1.f, TOK, 0, TOK, 0);

    // 3. P = exp(scale * Q@K^T)*2^-5 : M=N=HW, K=C
    dim3 gs(HWT / 128, HWT / 128, BATCH);
    mma_gemm<0><<<gs, 256, SMEM_T>>>(q, k, nullptr, nullptr, s, nullptr, nullptr,
        CCH, CCH, HWT, CCH, att_scale, TOK, TOK, SS, 0);

    // 4. o = (P@V) / rowsum(P) : M=HW, N=C, K=HW
    dim3 ga(CCH / 128, HWT / 128, BATCH);
    mma_gemm<2><<<ga, 256, SMEM_T>>>(s, v, nullptr, nullptr, o, nullptr, nullptr,
        HWT, HWT, CCH, HWT, 1.f, SS, TOK, TOK, 0);

    // 5. out = x + P_w @ o^T (channel-major): M=C, N=HW, K=C
    dim3 gp(HWT / 128, CCH / 128, BATCH);
    mma_gemm<3><<<gp, 256, SMEM_T>>>(pw, o, p_b, x, out, nullptr, nullptr,
        CCH, CCH, HWT, CCH, 1.f, 0, TOK, CHW, CHW);
}